// round 12
// baseline (speedup 1.0000x reference)
#include <cuda_runtime.h>
#include <cuda_bf16.h>
#include <cstdint>

#define C 128
#define NMAX 200000
#define EPSF 1e-5f

// ---------------- scratch ----------------
__device__ __align__(16) float        g_x[NMAX * C];
__device__ __align__(16) float        g_y[NMAX * C];
__device__ __align__(16) unsigned int g_p[NMAX * C];           // packed (bf16hi<<16)|bf16lo
__device__ __align__(16) unsigned int g_wfrag[4 * 27 * C * C]; // per-lane HMMA B fragments
__device__ __align__(16) float        g_cnt[NMAX];
__device__ __align__(16) float        g_stats[2 * C];
__device__ __align__(16) float        g_ss[2 * C];

// ---------------- helpers ----------------
__device__ __forceinline__ unsigned int packhl(float x) {
    __nv_bfloat16 h = __float2bfloat16(x);
    float hf = __bfloat162float(h);
    __nv_bfloat16 l = __float2bfloat16(x - hf);
    return ((unsigned int)__bfloat16_as_ushort(h) << 16) | (unsigned int)__bfloat16_as_ushort(l);
}
__device__ __forceinline__ void split16(float x, unsigned int& hi, unsigned int& lo) {
    __nv_bfloat16 h = __float2bfloat16(x);
    float hf = __bfloat162float(h);
    __nv_bfloat16 l = __float2bfloat16(x - hf);
    hi = (unsigned int)__bfloat16_as_ushort(h);
    lo = (unsigned int)__bfloat16_as_ushort(l);
}
__device__ __forceinline__ void mma_bf16(float* c, uint32_t a0, uint32_t a1, uint32_t a2, uint32_t a3,
                                         uint32_t b0, uint32_t b1) {
    asm volatile(
        "mma.sync.aligned.m16n8k16.row.col.f32.bf16.bf16.f32 "
        "{%0,%1,%2,%3}, {%4,%5,%6,%7}, {%8,%9}, {%0,%1,%2,%3};"
        : "+f"(c[0]), "+f"(c[1]), "+f"(c[2]), "+f"(c[3])
        : "r"(a0), "r"(a1), "r"(a2), "r"(a3), "r"(b0), "r"(b1));
}
__device__ __forceinline__ uint32_t smem_u32(const void* p) {
    uint32_t a;
    asm("{ .reg .u64 t; cvta.to.shared.u64 t, %1; cvt.u32.u64 %0, t; }" : "=r"(a) : "l"(p));
    return a;
}
__device__ __forceinline__ void cp_async16(uint32_t saddr, const void* g) {
    asm volatile("cp.async.cg.shared.global [%0], [%1], 16;" :: "r"(saddr), "l"(g));
}
__device__ __forceinline__ void cp_commit() { asm volatile("cp.async.commit_group;" ::: "memory"); }
template<int N> __device__ __forceinline__ void cp_wait() {
    asm volatile("cp.async.wait_group %0;" :: "n"(N) : "memory");
}

// ---------------- zero scratch ----------------
__global__ void zero_kernel(float* __restrict__ x, float* __restrict__ cnt, int M) {
    int stride = gridDim.x * blockDim.x;
    int tot = M * C;
    for (int i = blockIdx.x * blockDim.x + threadIdx.x; i < tot; i += stride) x[i] = 0.f;
    for (int i = blockIdx.x * blockDim.x + threadIdx.x; i < M;   i += stride) cnt[i] = 0.f;
}
__global__ void zero_stats_kernel(float* __restrict__ s) {
    if (threadIdx.x < 2 * C) s[threadIdx.x] = 0.f;
}

// ---------------- weight -> HMMA B fragments ----------------
__global__ void wfrag_kernel(const float* __restrict__ w, uint4* __restrict__ out, int total4) {
    for (int i = blockIdx.x * blockDim.x + threadIdx.x; i < total4; i += gridDim.x * blockDim.x) {
        int lane = i & 31;
        int nt = (i >> 5) & 15;
        int ks = (i >> 9) & 7;
        int o = (i >> 12) % 27;
        int s = i / 110592;
        int k0 = ks * 16 + (lane & 3) * 2;
        int n = nt * 8 + (lane >> 2);
        const float* src = w + ((size_t)(s * 27 + o) << 14);
        unsigned int h00, l00, h01, l01, h10, l10, h11, l11;
        split16(src[(k0 + 0) * 128 + n], h00, l00);
        split16(src[(k0 + 1) * 128 + n], h01, l01);
        split16(src[(k0 + 8) * 128 + n], h10, l10);
        split16(src[(k0 + 9) * 128 + n], h11, l11);
        out[i] = make_uint4(h00 | (h01 << 16), h10 | (h11 << 16),
                            l00 | (l01 << 16), l10 | (l11 << 16));
    }
}

// ---------------- encoder ----------------
__global__ __launch_bounds__(256) void encoder_kernel(
    const float* __restrict__ gp, const float* __restrict__ w_enc,
    const float* __restrict__ b_enc, const float* __restrict__ ln_g,
    const float* __restrict__ ln_b, const int* __restrict__ inv,
    float* __restrict__ xsum, float* __restrict__ cnt, int N)
{
    __shared__ __align__(16) float shW[14 * C];
    for (int i = threadIdx.x; i < 14 * C; i += blockDim.x) shW[i] = w_enc[i];
    __syncthreads();
    const int lane = threadIdx.x & 31;
    const int gw = (blockIdx.x * blockDim.x + threadIdx.x) >> 5;
    const int nw = (gridDim.x * blockDim.x) >> 5;
    for (int p = gw; p < N; p += nw) {
        float gv[14];
#pragma unroll
        for (int k = 0; k < 14; ++k) gv[k] = __ldg(&gp[p * 14 + k]);
        float f[4];
#pragma unroll
        for (int j = 0; j < 4; ++j) {
            int c = lane + 32 * j;
            float acc = __ldg(&b_enc[c]);
#pragma unroll
            for (int k = 0; k < 14; ++k) acc = fmaf(gv[k], shW[k * C + c], acc);
            f[j] = acc;
        }
        float s = f[0] + f[1] + f[2] + f[3];
        float s2 = f[0]*f[0] + f[1]*f[1] + f[2]*f[2] + f[3]*f[3];
#pragma unroll
        for (int m = 16; m; m >>= 1) {
            s  += __shfl_xor_sync(0xffffffffu, s,  m);
            s2 += __shfl_xor_sync(0xffffffffu, s2, m);
        }
        float mean = s * (1.f / C);
        float var = s2 * (1.f / C) - mean * mean;
        float rs = rsqrtf(var + EPSF);
        int v = inv[p];
        float* base = xsum + (size_t)v * C;
#pragma unroll
        for (int j = 0; j < 4; ++j) {
            int c = lane + 32 * j;
            float yv = fmaf((f[j] - mean) * rs, __ldg(&ln_g[c]), __ldg(&ln_b[c]));
            yv = fmaxf(yv, 0.f);
            atomicAdd(&base[c], yv);
        }
        if (lane == 0) atomicAdd(&cnt[v], 1.f);
    }
}

// ---------------- segment mean + pack ----------------
__global__ void divide_pack_kernel(float* __restrict__ x, const float* __restrict__ cnt,
                                   unsigned int* __restrict__ xp, int total) {
    int stride = gridDim.x * blockDim.x;
    for (int i = blockIdx.x * blockDim.x + threadIdx.x; i < total; i += stride) {
        float v = x[i] / cnt[i >> 7];
        x[i] = v;
        xp[i] = packhl(v);
    }
}

// ---------------- HMMA submanifold conv, cp.async pipelined ----------------
// CTA: 256 voxels, 512 threads (16 warps). Triple-buffered W (cp.async prefetch of o+2),
// software-pipelined A gather, 3-pass hi/lo bf16 MMA.
#define CONV_SMEM (3 * 65536)
__global__ __launch_bounds__(512, 1) void conv_mma_kernel(
    const unsigned int* __restrict__ xp, float* __restrict__ y,
    const uint4* __restrict__ wfrag,        // [27][8][16][32] uint4
    const int* __restrict__ nbr_idx, const float* __restrict__ nbr_mask, int M)
{
    extern __shared__ __align__(16) char smem[];
    uint4* shW = (uint4*)smem;              // 3 bufs x 4096 uint4
    const uint32_t sbase = smem_u32(smem);

    const int tid = threadIdx.x;
    const int lane = tid & 31;
    const int wid = tid >> 5;
    const int qr = lane >> 2;
    const int col0 = (lane & 3) * 2;

    const int vbase = blockIdx.x * 256 + wid * 16;
    const int v0 = vbase + qr;
    const int v1 = v0 + 8;

    float acc[16][4];
#pragma unroll
    for (int nt = 0; nt < 16; ++nt) {
        acc[nt][0] = 0.f; acc[nt][1] = 0.f; acc[nt][2] = 0.f; acc[nt][3] = 0.f;
    }

    // prologue: stage W[0] and W[1]
    {
        const uint4* s0 = wfrag + 0 * 4096 + tid;
#pragma unroll
        for (int j = 0; j < 8; ++j)
            cp_async16(sbase + (uint32_t)(0 * 4096 + tid + j * 512) * 16, s0 + j * 512);
        cp_commit();
        const uint4* s1 = wfrag + 1 * 4096 + tid;
#pragma unroll
        for (int j = 0; j < 8; ++j)
            cp_async16(sbase + (uint32_t)(1 * 4096 + tid + j * 512) * 16, s1 + j * 512);
        cp_commit();
    }
    // neighbor info for o=0
    bool ok0 = false, ok1 = false;
    int nb0 = 0, nb1 = 0;
    if (v0 < M && __ldg(&nbr_mask[(size_t)v0 * 27 + 0]) != 0.f) { ok0 = true; nb0 = __ldg(&nbr_idx[(size_t)v0 * 27 + 0]); }
    if (v1 < M && __ldg(&nbr_mask[(size_t)v1 * 27 + 0]) != 0.f) { ok1 = true; nb1 = __ldg(&nbr_idx[(size_t)v1 * 27 + 0]); }

    int bsel = 0;      // buffer holding W[o]
    int bnext = 2;     // buffer to fill with W[o+2]
#pragma unroll 1
    for (int o = 0; o < 27; ++o) {
        cp_wait<1>();          // W[o] arrived (this thread's share)
        __syncthreads();       // all shares visible; all warps done computing o-1 (freed buf bnext)
        // prefetch W[o+2] into bnext
        if (o + 2 < 27) {
            const uint4* s = wfrag + (o + 2) * 4096 + tid;
#pragma unroll
            for (int j = 0; j < 8; ++j)
                cp_async16(sbase + (uint32_t)(bnext * 4096 + tid + j * 512) * 16, s + j * 512);
        }
        cp_commit();           // commit (possibly empty) to keep group count uniform
        // prefetch neighbor info for o+1
        bool pok0 = false, pok1 = false;
        int pnb0 = 0, pnb1 = 0;
        if (o + 1 < 27) {
            if (v0 < M && __ldg(&nbr_mask[(size_t)v0 * 27 + o + 1]) != 0.f) { pok0 = true; pnb0 = __ldg(&nbr_idx[(size_t)v0 * 27 + o + 1]); }
            if (v1 < M && __ldg(&nbr_mask[(size_t)v1 * 27 + o + 1]) != 0.f) { pok1 = true; pnb1 = __ldg(&nbr_idx[(size_t)v1 * 27 + o + 1]); }
        }
        int anyw = __any_sync(0xffffffffu, ok0 || ok1);
        if (anyw) {
            const unsigned int* p0 = xp + ((size_t)nb0 << 7);
            const unsigned int* p1 = xp + ((size_t)nb1 << 7);
            const uint2 z2 = make_uint2(0u, 0u);
            const uint4* wbase = shW + bsel * 4096 + lane;
            // pipeline: load ks=0
            uint2 r0a = ok0 ? *(const uint2*)(p0 + col0)     : z2;
            uint2 r0b = ok0 ? *(const uint2*)(p0 + col0 + 8) : z2;
            uint2 r1a = ok1 ? *(const uint2*)(p1 + col0)     : z2;
            uint2 r1b = ok1 ? *(const uint2*)(p1 + col0 + 8) : z2;
#pragma unroll
            for (int ks = 0; ks < 8; ++ks) {
                uint2 n0a, n0b, n1a, n1b;
                if (ks < 7) {
                    int k0 = (ks + 1) * 16 + col0;
                    n0a = ok0 ? *(const uint2*)(p0 + k0)     : z2;
                    n0b = ok0 ? *(const uint2*)(p0 + k0 + 8) : z2;
                    n1a = ok1 ? *(const uint2*)(p1 + k0)     : z2;
                    n1b = ok1 ? *(const uint2*)(p1 + k0 + 8) : z2;
                }
                uint32_t a0h = __byte_perm(r0a.x, r0a.y, 0x7632);
                uint32_t a1h = __byte_perm(r1a.x, r1a.y, 0x7632);
                uint32_t a2h = __byte_perm(r0b.x, r0b.y, 0x7632);
                uint32_t a3h = __byte_perm(r1b.x, r1b.y, 0x7632);
                uint32_t a0l = __byte_perm(r0a.x, r0a.y, 0x5410);
                uint32_t a1l = __byte_perm(r1a.x, r1a.y, 0x5410);
                uint32_t a2l = __byte_perm(r0b.x, r0b.y, 0x5410);
                uint32_t a3l = __byte_perm(r1b.x, r1b.y, 0x5410);
                const uint4* wrow = wbase + (ks * 16) * 32;
#pragma unroll
                for (int nt = 0; nt < 16; ++nt) {
                    uint4 wb = wrow[nt * 32];
                    mma_bf16(acc[nt], a0h, a1h, a2h, a3h, wb.x, wb.y);
                    mma_bf16(acc[nt], a0h, a1h, a2h, a3h, wb.z, wb.w);
                    mma_bf16(acc[nt], a0l, a1l, a2l, a3l, wb.x, wb.y);
                }
                r0a = n0a; r0b = n0b; r1a = n1a; r1b = n1b;
            }
        }
        ok0 = pok0; ok1 = pok1; nb0 = pnb0; nb1 = pnb1;
        bsel = (bsel + 1) % 3;
        bnext = (bnext + 1) % 3;
    }
#pragma unroll
    for (int nt = 0; nt < 16; ++nt) {
        if (v0 < M)
            *(float2*)(y + ((size_t)v0 << 7) + nt * 8 + col0) = make_float2(acc[nt][0], acc[nt][1]);
        if (v1 < M)
            *(float2*)(y + ((size_t)v1 << 7) + nt * 8 + col0) = make_float2(acc[nt][2], acc[nt][3]);
    }
}

// ---------------- BN ----------------
__global__ __launch_bounds__(128) void bnstats_kernel(
    const float* __restrict__ y, float* __restrict__ stats, int M)
{
    int c = threadIdx.x;
    float s = 0.f, s2 = 0.f;
    for (int r = blockIdx.x; r < M; r += gridDim.x) {
        float v = y[(size_t)r * C + c];
        s += v; s2 += v * v;
    }
    atomicAdd(&stats[c], s);
    atomicAdd(&stats[C + c], s2);
}

__global__ void bnfinalize_kernel(
    const float* __restrict__ stats, const float* __restrict__ g,
    const float* __restrict__ b, float* __restrict__ ss, int M)
{
    int c = threadIdx.x;
    if (c < C) {
        float invM = 1.f / (float)M;
        float mean = stats[c] * invM;
        float var = stats[C + c] * invM - mean * mean;
        float sc = g[c] * rsqrtf(var + EPSF);
        ss[c] = sc;
        ss[C + c] = b[c] - mean * sc;
    }
}

__global__ void bnapply_kernel(
    const float* __restrict__ yin, const float* __restrict__ ss,
    const float* __restrict__ resid, float* __restrict__ outf,
    unsigned int* __restrict__ outp, int total)
{
    int stride = gridDim.x * blockDim.x;
    for (int i = blockIdx.x * blockDim.x + threadIdx.x; i < total; i += stride) {
        int c = i & (C - 1);
        float v = fmaf(yin[i], ss[c], ss[C + c]);
        if (resid) v += resid[i];
        v = fmaxf(v, 0.f);
        if (outf) outf[i] = v;
        outp[i] = packhl(v);
    }
}

// ---------------- head ----------------
__global__ __launch_bounds__(256) void head_kernel(
    const float* __restrict__ x, const int* __restrict__ inv,
    const float* __restrict__ gp, const float* __restrict__ w1,
    const float* __restrict__ b1, const float* __restrict__ w2,
    const float* __restrict__ b2, float* __restrict__ out, int N)
{
    __shared__ __align__(16) float shW1[C * 64];
    __shared__ __align__(16) float shW2[64 * 14];
    __shared__ __align__(16) float shB1[64];
    __shared__ __align__(16) float shB2[16];
    __shared__ __align__(16) float shPF[8][C];
    __shared__ __align__(16) float shH[8][64];
    for (int i = threadIdx.x; i < C * 64; i += 256) shW1[i] = w1[i];
    for (int i = threadIdx.x; i < 64 * 14; i += 256) shW2[i] = w2[i];
    if (threadIdx.x < 64) shB1[threadIdx.x] = b1[threadIdx.x];
    if (threadIdx.x < 14) shB2[threadIdx.x] = b2[threadIdx.x];
    __syncthreads();
    const int lane = threadIdx.x & 31;
    const int w = threadIdx.x >> 5;
    const int gw = (blockIdx.x * 256 + threadIdx.x) >> 5;
    const int nw = gridDim.x * 8;
    for (int p = gw; p < N; p += nw) {
        int v = inv[p];
        ((float4*)shPF[w])[lane] = ((const float4*)(x + (size_t)v * C))[lane];
        __syncwarp();
        float h0 = shB1[lane], h1 = shB1[lane + 32];
#pragma unroll 8
        for (int k = 0; k < C; ++k) {
            float a = shPF[w][k];
            h0 = fmaf(a, shW1[k * 64 + lane], h0);
            h1 = fmaf(a, shW1[k * 64 + lane + 32], h1);
        }
        h0 = fmaxf(h0, 0.f); h1 = fmaxf(h1, 0.f);
        shH[w][lane] = h0; shH[w][lane + 32] = h1;
        __syncwarp();
        if (lane < 14) {
            float d = shB2[lane];
#pragma unroll
            for (int j = 0; j < 64; ++j) d = fmaf(shH[w][j], shW2[j * 14 + lane], d);
            out[p * 14 + lane] = gp[p * 14 + lane] + d;
        }
        __syncwarp();
    }
}

// ---------------- launch ----------------
extern "C" void kernel_launch(void* const* d_in, const int* in_sizes, int n_in,
                              void* d_out, int out_size)
{
    const float* gp       = (const float*)d_in[0];
    const float* w_enc    = (const float*)d_in[1];
    const float* b_enc    = (const float*)d_in[2];
    const float* ln_g     = (const float*)d_in[3];
    const float* ln_b     = (const float*)d_in[4];
    const float* conv_w   = (const float*)d_in[5];
    const float* bn_g     = (const float*)d_in[6];
    const float* bn_b     = (const float*)d_in[7];
    const float* w1       = (const float*)d_in[8];
    const float* b1       = (const float*)d_in[9];
    const float* w2       = (const float*)d_in[10];
    const float* b2       = (const float*)d_in[11];
    const float* nbr_mask = (const float*)d_in[12];
    const int*   inv_idx  = (const int*)d_in[13];
    const int*   nbr_idx  = (const int*)d_in[14];
    float* out = (float*)d_out;

    const int N = in_sizes[0] / 14;
    const int M = in_sizes[12] / 27;

    float *px, *py, *pcnt, *pstats, *pss;
    unsigned int *pp, *pwf;
    cudaGetSymbolAddress((void**)&px,     g_x);
    cudaGetSymbolAddress((void**)&py,     g_y);
    cudaGetSymbolAddress((void**)&pp,     g_p);
    cudaGetSymbolAddress((void**)&pwf,    g_wfrag);
    cudaGetSymbolAddress((void**)&pcnt,   g_cnt);
    cudaGetSymbolAddress((void**)&pstats, g_stats);
    cudaGetSymbolAddress((void**)&pss,    g_ss);

    cudaFuncSetAttribute(conv_mma_kernel, cudaFuncAttributeMaxDynamicSharedMemorySize, CONV_SMEM);

    wfrag_kernel<<<1728, 256>>>(conv_w, (uint4*)pwf, 4 * 110592);

    zero_kernel<<<1184, 256>>>(px, pcnt, M);
    encoder_kernel<<<1024, 256>>>(gp, w_enc, b_enc, ln_g, ln_b, inv_idx, px, pcnt, N);
    divide_pack_kernel<<<1184, 256>>>(px, pcnt, pp, M * C);

    const int convGrid = (M + 255) / 256;
    const uint4* wf = (const uint4*)pwf;
    // stage 0
    conv_mma_kernel<<<convGrid, 512, CONV_SMEM>>>(pp, py, wf + 0 * 110592, nbr_idx, nbr_mask, M);
    zero_stats_kernel<<<1, 256>>>(pstats);
    bnstats_kernel<<<1024, 128>>>(py, pstats, M);
    bnfinalize_kernel<<<1, 128>>>(pstats, bn_g + 0 * C, bn_b + 0 * C, pss, M);
    bnapply_kernel<<<1184, 256>>>(py, pss, nullptr, nullptr, pp, M * C);
    // stage 1 (+ residual x)
    conv_mma_kernel<<<convGrid, 512, CONV_SMEM>>>(pp, py, wf + 1 * 110592, nbr_idx, nbr_mask, M);
    zero_stats_kernel<<<1, 256>>>(pstats);
    bnstats_kernel<<<1024, 128>>>(py, pstats, M);
    bnfinalize_kernel<<<1, 128>>>(pstats, bn_g + 1 * C, bn_b + 1 * C, pss, M);
    bnapply_kernel<<<1184, 256>>>(py, pss, px, px, pp, M * C);
    // stage 2
    conv_mma_kernel<<<convGrid, 512, CONV_SMEM>>>(pp, py, wf + 2 * 110592, nbr_idx, nbr_mask, M);
    zero_stats_kernel<<<1, 256>>>(pstats);
    bnstats_kernel<<<1024, 128>>>(py, pstats, M);
    bnfinalize_kernel<<<1, 128>>>(pstats, bn_g + 2 * C, bn_b + 2 * C, pss, M);
    bnapply_kernel<<<1184, 256>>>(py, pss, nullptr, nullptr, pp, M * C);
    // stage 3 (+ residual x)
    conv_mma_kernel<<<convGrid, 512, CONV_SMEM>>>(pp, py, wf + 3 * 110592, nbr_idx, nbr_mask, M);
    zero_stats_kernel<<<1, 256>>>(pstats);
    bnstats_kernel<<<1024, 128>>>(py, pstats, M);
    bnfinalize_kernel<<<1, 128>>>(pstats, bn_g + 3 * C, bn_b + 3 * C, pss, M);
    bnapply_kernel<<<1184, 256>>>(py, pss, px, px, pp, M * C);

    head_kernel<<<1024, 256>>>(px, inv_idx, gp, w1, b1, w2, b2, out, N);
}

// round 13
// speedup vs baseline: 1.2415x; 1.2415x over previous
#include <cuda_runtime.h>
#include <cuda_bf16.h>
#include <cstdint>

#define C 128
#define NMAX 200000
#define EPSF 1e-5f

// ---------------- scratch ----------------
__device__ __align__(16) float        g_x[NMAX * C];
__device__ __align__(16) float        g_y[NMAX * C];
__device__ __align__(16) unsigned int g_p[NMAX * C];           // packed (bf16hi<<16)|bf16lo
__device__ __align__(16) unsigned int g_wfrag[4 * 27 * C * C]; // per-lane HMMA B fragments
__device__ __align__(16) float        g_cnt[NMAX];
__device__ __align__(16) float        g_stats[2 * C];
__device__ __align__(16) float        g_ss[2 * C];

// ---------------- helpers ----------------
__device__ __forceinline__ unsigned int packhl(float x) {
    __nv_bfloat16 h = __float2bfloat16(x);
    float hf = __bfloat162float(h);
    __nv_bfloat16 l = __float2bfloat16(x - hf);
    return ((unsigned int)__bfloat16_as_ushort(h) << 16) | (unsigned int)__bfloat16_as_ushort(l);
}
__device__ __forceinline__ void split16(float x, unsigned int& hi, unsigned int& lo) {
    __nv_bfloat16 h = __float2bfloat16(x);
    float hf = __bfloat162float(h);
    __nv_bfloat16 l = __float2bfloat16(x - hf);
    hi = (unsigned int)__bfloat16_as_ushort(h);
    lo = (unsigned int)__bfloat16_as_ushort(l);
}
__device__ __forceinline__ void mma_bf16(float* c, uint32_t a0, uint32_t a1, uint32_t a2, uint32_t a3,
                                         uint32_t b0, uint32_t b1) {
    asm volatile(
        "mma.sync.aligned.m16n8k16.row.col.f32.bf16.bf16.f32 "
        "{%0,%1,%2,%3}, {%4,%5,%6,%7}, {%8,%9}, {%0,%1,%2,%3};"
        : "+f"(c[0]), "+f"(c[1]), "+f"(c[2]), "+f"(c[3])
        : "r"(a0), "r"(a1), "r"(a2), "r"(a3), "r"(b0), "r"(b1));
}

// ---------------- zero scratch ----------------
__global__ void zero_kernel(float* __restrict__ x, float* __restrict__ cnt, int M) {
    int stride = gridDim.x * blockDim.x;
    int tot = M * C;
    for (int i = blockIdx.x * blockDim.x + threadIdx.x; i < tot; i += stride) x[i] = 0.f;
    for (int i = blockIdx.x * blockDim.x + threadIdx.x; i < M;   i += stride) cnt[i] = 0.f;
}
__global__ void zero_stats_kernel(float* __restrict__ s) {
    if (threadIdx.x < 2 * C) s[threadIdx.x] = 0.f;
}

// ---------------- weight -> HMMA B fragments ----------------
__global__ void wfrag_kernel(const float* __restrict__ w, uint4* __restrict__ out, int total4) {
    for (int i = blockIdx.x * blockDim.x + threadIdx.x; i < total4; i += gridDim.x * blockDim.x) {
        int lane = i & 31;
        int nt = (i >> 5) & 15;
        int ks = (i >> 9) & 7;
        int o = (i >> 12) % 27;
        int s = i / 110592;
        int k0 = ks * 16 + (lane & 3) * 2;
        int n = nt * 8 + (lane >> 2);
        const float* src = w + ((size_t)(s * 27 + o) << 14);
        unsigned int h00, l00, h01, l01, h10, l10, h11, l11;
        split16(src[(k0 + 0) * 128 + n], h00, l00);
        split16(src[(k0 + 1) * 128 + n], h01, l01);
        split16(src[(k0 + 8) * 128 + n], h10, l10);
        split16(src[(k0 + 9) * 128 + n], h11, l11);
        out[i] = make_uint4(h00 | (h01 << 16), h10 | (h11 << 16),
                            l00 | (l01 << 16), l10 | (l11 << 16));
    }
}

// ---------------- encoder ----------------
__global__ __launch_bounds__(256) void encoder_kernel(
    const float* __restrict__ gp, const float* __restrict__ w_enc,
    const float* __restrict__ b_enc, const float* __restrict__ ln_g,
    const float* __restrict__ ln_b, const int* __restrict__ inv,
    float* __restrict__ xsum, float* __restrict__ cnt, int N)
{
    __shared__ __align__(16) float shW[14 * C];
    for (int i = threadIdx.x; i < 14 * C; i += blockDim.x) shW[i] = w_enc[i];
    __syncthreads();
    const int lane = threadIdx.x & 31;
    const int gw = (blockIdx.x * blockDim.x + threadIdx.x) >> 5;
    const int nw = (gridDim.x * blockDim.x) >> 5;
    for (int p = gw; p < N; p += nw) {
        float gv[14];
#pragma unroll
        for (int k = 0; k < 14; ++k) gv[k] = __ldg(&gp[p * 14 + k]);
        float f[4];
#pragma unroll
        for (int j = 0; j < 4; ++j) {
            int c = lane + 32 * j;
            float acc = __ldg(&b_enc[c]);
#pragma unroll
            for (int k = 0; k < 14; ++k) acc = fmaf(gv[k], shW[k * C + c], acc);
            f[j] = acc;
        }
        float s = f[0] + f[1] + f[2] + f[3];
        float s2 = f[0]*f[0] + f[1]*f[1] + f[2]*f[2] + f[3]*f[3];
#pragma unroll
        for (int m = 16; m; m >>= 1) {
            s  += __shfl_xor_sync(0xffffffffu, s,  m);
            s2 += __shfl_xor_sync(0xffffffffu, s2, m);
        }
        float mean = s * (1.f / C);
        float var = s2 * (1.f / C) - mean * mean;
        float rs = rsqrtf(var + EPSF);
        int v = inv[p];
        float* base = xsum + (size_t)v * C;
#pragma unroll
        for (int j = 0; j < 4; ++j) {
            int c = lane + 32 * j;
            float yv = fmaf((f[j] - mean) * rs, __ldg(&ln_g[c]), __ldg(&ln_b[c]));
            yv = fmaxf(yv, 0.f);
            atomicAdd(&base[c], yv);
        }
        if (lane == 0) atomicAdd(&cnt[v], 1.f);
    }
}

// ---------------- segment mean + pack ----------------
__global__ void divide_pack_kernel(float* __restrict__ x, const float* __restrict__ cnt,
                                   unsigned int* __restrict__ xp, int total) {
    int stride = gridDim.x * blockDim.x;
    for (int i = blockIdx.x * blockDim.x + threadIdx.x; i < total; i += stride) {
        float v = x[i] / cnt[i >> 7];
        x[i] = v;
        xp[i] = packhl(v);
    }
}

// ---------------- HMMA submanifold conv (+ fused BN stats) ----------------
// CTA: 256 voxels, 512 threads (16 warps). Single 64KB W buffer (preserves L1D for
// A-row gather reuse), block-level W skip, register-pipelined A loads + neighbor
// prefetch, 3-pass hi/lo bf16 MMA. Epilogue accumulates per-channel sum/sumsq.
#define CONV_SMEM (65536 + 128 + 1024)
__global__ __launch_bounds__(512, 1) void conv_mma_kernel(
    const unsigned int* __restrict__ xp, float* __restrict__ y,
    const uint4* __restrict__ wfrag,        // [27][8][16][32] uint4
    const int* __restrict__ nbr_idx, const float* __restrict__ nbr_mask,
    float* __restrict__ stats, int M)
{
    extern __shared__ __align__(16) char smem[];
    uint4* shW = (uint4*)smem;                    // 4096 uint4 (64 KB)
    int* shFlag = (int*)(smem + 65536);           // 16 warp flags
    float* shStats = (float*)(smem + 65536 + 128);// 256 floats

    const int tid = threadIdx.x;
    const int wid = tid >> 5;
    const int lane = tid & 31;
    const int qr = lane >> 2;
    const int col0 = (lane & 3) * 2;

    const int vbase = blockIdx.x * 256 + wid * 16;
    const int v0 = vbase + qr;
    const int v1 = v0 + 8;

    if (tid < 256) shStats[tid] = 0.f;

    float acc[16][4];
#pragma unroll
    for (int nt = 0; nt < 16; ++nt) {
        acc[nt][0] = 0.f; acc[nt][1] = 0.f; acc[nt][2] = 0.f; acc[nt][3] = 0.f;
    }

    // neighbor info for o=0
    bool ok0 = false, ok1 = false;
    int nb0 = 0, nb1 = 0;
    if (v0 < M && __ldg(&nbr_mask[(size_t)v0 * 27 + 0]) != 0.f) { ok0 = true; nb0 = __ldg(&nbr_idx[(size_t)v0 * 27 + 0]); }
    if (v1 < M && __ldg(&nbr_mask[(size_t)v1 * 27 + 0]) != 0.f) { ok1 = true; nb1 = __ldg(&nbr_idx[(size_t)v1 * 27 + 0]); }

#pragma unroll 1
    for (int o = 0; o < 27; ++o) {
        int anyw = __any_sync(0xffffffffu, ok0 || ok1);
        if (lane == 0) shFlag[wid] = anyw;
        __syncthreads();   // flags visible; previous offset's compute done (shW free)
        int blockany = 0;
#pragma unroll
        for (int w = 0; w < 16; ++w) blockany |= shFlag[w];
        if (blockany) {
            const uint4* src = wfrag + o * 4096;
            for (int i = tid; i < 4096; i += 512) shW[i] = __ldg(&src[i]);
        }
        // prefetch neighbor info for o+1 (latency overlaps the barrier + compute)
        bool pok0 = false, pok1 = false;
        int pnb0 = 0, pnb1 = 0;
        if (o + 1 < 27) {
            if (v0 < M && __ldg(&nbr_mask[(size_t)v0 * 27 + o + 1]) != 0.f) { pok0 = true; pnb0 = __ldg(&nbr_idx[(size_t)v0 * 27 + o + 1]); }
            if (v1 < M && __ldg(&nbr_mask[(size_t)v1 * 27 + o + 1]) != 0.f) { pok1 = true; pnb1 = __ldg(&nbr_idx[(size_t)v1 * 27 + o + 1]); }
        }
        __syncthreads();
        if (anyw) {
            const unsigned int* p0 = xp + ((size_t)nb0 << 7);
            const unsigned int* p1 = xp + ((size_t)nb1 << 7);
            const uint2 z2 = make_uint2(0u, 0u);
            const uint4* wbase = shW + lane;
            // software pipeline: load ks=0
            uint2 r0a = ok0 ? *(const uint2*)(p0 + col0)     : z2;
            uint2 r0b = ok0 ? *(const uint2*)(p0 + col0 + 8) : z2;
            uint2 r1a = ok1 ? *(const uint2*)(p1 + col0)     : z2;
            uint2 r1b = ok1 ? *(const uint2*)(p1 + col0 + 8) : z2;
#pragma unroll
            for (int ks = 0; ks < 8; ++ks) {
                uint2 n0a, n0b, n1a, n1b;
                if (ks < 7) {
                    int k0 = (ks + 1) * 16 + col0;
                    n0a = ok0 ? *(const uint2*)(p0 + k0)     : z2;
                    n0b = ok0 ? *(const uint2*)(p0 + k0 + 8) : z2;
                    n1a = ok1 ? *(const uint2*)(p1 + k0)     : z2;
                    n1b = ok1 ? *(const uint2*)(p1 + k0 + 8) : z2;
                }
                uint32_t a0h = __byte_perm(r0a.x, r0a.y, 0x7632);
                uint32_t a1h = __byte_perm(r1a.x, r1a.y, 0x7632);
                uint32_t a2h = __byte_perm(r0b.x, r0b.y, 0x7632);
                uint32_t a3h = __byte_perm(r1b.x, r1b.y, 0x7632);
                uint32_t a0l = __byte_perm(r0a.x, r0a.y, 0x5410);
                uint32_t a1l = __byte_perm(r1a.x, r1a.y, 0x5410);
                uint32_t a2l = __byte_perm(r0b.x, r0b.y, 0x5410);
                uint32_t a3l = __byte_perm(r1b.x, r1b.y, 0x5410);
                const uint4* wrow = wbase + (ks * 16) * 32;
#pragma unroll
                for (int nt = 0; nt < 16; ++nt) {
                    uint4 wb = wrow[nt * 32];
                    mma_bf16(acc[nt], a0h, a1h, a2h, a3h, wb.x, wb.y);
                    mma_bf16(acc[nt], a0h, a1h, a2h, a3h, wb.z, wb.w);
                    mma_bf16(acc[nt], a0l, a1l, a2l, a3l, wb.x, wb.y);
                }
                r0a = n0a; r0b = n0b; r1a = n1a; r1b = n1b;
            }
        }
        ok0 = pok0; ok1 = pok1; nb0 = pnb0; nb1 = pnb1;
    }

    // store y + accumulate BN stats (acc rows beyond M are exactly zero)
#pragma unroll
    for (int nt = 0; nt < 16; ++nt) {
        if (v0 < M)
            *(float2*)(y + ((size_t)v0 << 7) + nt * 8 + col0) = make_float2(acc[nt][0], acc[nt][1]);
        if (v1 < M)
            *(float2*)(y + ((size_t)v1 << 7) + nt * 8 + col0) = make_float2(acc[nt][2], acc[nt][3]);
        int c = nt * 8 + col0;
        atomicAdd(&shStats[c],           acc[nt][0] + acc[nt][2]);
        atomicAdd(&shStats[128 + c],     acc[nt][0] * acc[nt][0] + acc[nt][2] * acc[nt][2]);
        atomicAdd(&shStats[c + 1],       acc[nt][1] + acc[nt][3]);
        atomicAdd(&shStats[128 + c + 1], acc[nt][1] * acc[nt][1] + acc[nt][3] * acc[nt][3]);
    }
    __syncthreads();
    if (tid < 256) atomicAdd(&stats[tid], shStats[tid]);
}

// ---------------- BN finalize / apply ----------------
__global__ void bnfinalize_kernel(
    const float* __restrict__ stats, const float* __restrict__ g,
    const float* __restrict__ b, float* __restrict__ ss, int M)
{
    int c = threadIdx.x;
    if (c < C) {
        float invM = 1.f / (float)M;
        float mean = stats[c] * invM;
        float var = stats[C + c] * invM - mean * mean;
        float sc = g[c] * rsqrtf(var + EPSF);
        ss[c] = sc;
        ss[C + c] = b[c] - mean * sc;
    }
}

__global__ void bnapply_kernel(
    const float* __restrict__ yin, const float* __restrict__ ss,
    const float* __restrict__ resid, float* __restrict__ outf,
    unsigned int* __restrict__ outp, int total)
{
    int stride = gridDim.x * blockDim.x;
    for (int i = blockIdx.x * blockDim.x + threadIdx.x; i < total; i += stride) {
        int c = i & (C - 1);
        float v = fmaf(yin[i], ss[c], ss[C + c]);
        if (resid) v += resid[i];
        v = fmaxf(v, 0.f);
        if (outf) outf[i] = v;
        outp[i] = packhl(v);
    }
}

// ---------------- head ----------------
__global__ __launch_bounds__(256) void head_kernel(
    const float* __restrict__ x, const int* __restrict__ inv,
    const float* __restrict__ gp, const float* __restrict__ w1,
    const float* __restrict__ b1, const float* __restrict__ w2,
    const float* __restrict__ b2, float* __restrict__ out, int N)
{
    __shared__ __align__(16) float shW1[C * 64];
    __shared__ __align__(16) float shW2[64 * 14];
    __shared__ __align__(16) float shB1[64];
    __shared__ __align__(16) float shB2[16];
    __shared__ __align__(16) float shPF[8][C];
    __shared__ __align__(16) float shH[8][64];
    for (int i = threadIdx.x; i < C * 64; i += 256) shW1[i] = w1[i];
    for (int i = threadIdx.x; i < 64 * 14; i += 256) shW2[i] = w2[i];
    if (threadIdx.x < 64) shB1[threadIdx.x] = b1[threadIdx.x];
    if (threadIdx.x < 14) shB2[threadIdx.x] = b2[threadIdx.x];
    __syncthreads();
    const int lane = threadIdx.x & 31;
    const int w = threadIdx.x >> 5;
    const int gw = (blockIdx.x * 256 + threadIdx.x) >> 5;
    const int nw = gridDim.x * 8;
    for (int p = gw; p < N; p += nw) {
        int v = inv[p];
        ((float4*)shPF[w])[lane] = ((const float4*)(x + (size_t)v * C))[lane];
        __syncwarp();
        float h0 = shB1[lane], h1 = shB1[lane + 32];
#pragma unroll 8
        for (int k = 0; k < C; ++k) {
            float a = shPF[w][k];
            h0 = fmaf(a, shW1[k * 64 + lane], h0);
            h1 = fmaf(a, shW1[k * 64 + lane + 32], h1);
        }
        h0 = fmaxf(h0, 0.f); h1 = fmaxf(h1, 0.f);
        shH[w][lane] = h0; shH[w][lane + 32] = h1;
        __syncwarp();
        if (lane < 14) {
            float d = shB2[lane];
#pragma unroll
            for (int j = 0; j < 64; ++j) d = fmaf(shH[w][j], shW2[j * 14 + lane], d);
            out[p * 14 + lane] = gp[p * 14 + lane] + d;
        }
        __syncwarp();
    }
}

// ---------------- launch ----------------
extern "C" void kernel_launch(void* const* d_in, const int* in_sizes, int n_in,
                              void* d_out, int out_size)
{
    const float* gp       = (const float*)d_in[0];
    const float* w_enc    = (const float*)d_in[1];
    const float* b_enc    = (const float*)d_in[2];
    const float* ln_g     = (const float*)d_in[3];
    const float* ln_b     = (const float*)d_in[4];
    const float* conv_w   = (const float*)d_in[5];
    const float* bn_g     = (const float*)d_in[6];
    const float* bn_b     = (const float*)d_in[7];
    const float* w1       = (const float*)d_in[8];
    const float* b1       = (const float*)d_in[9];
    const float* w2       = (const float*)d_in[10];
    const float* b2       = (const float*)d_in[11];
    const float* nbr_mask = (const float*)d_in[12];
    const int*   inv_idx  = (const int*)d_in[13];
    const int*   nbr_idx  = (const int*)d_in[14];
    float* out = (float*)d_out;

    const int N = in_sizes[0] / 14;
    const int M = in_sizes[12] / 27;

    float *px, *py, *pcnt, *pstats, *pss;
    unsigned int *pp, *pwf;
    cudaGetSymbolAddress((void**)&px,     g_x);
    cudaGetSymbolAddress((void**)&py,     g_y);
    cudaGetSymbolAddress((void**)&pp,     g_p);
    cudaGetSymbolAddress((void**)&pwf,    g_wfrag);
    cudaGetSymbolAddress((void**)&pcnt,   g_cnt);
    cudaGetSymbolAddress((void**)&pstats, g_stats);
    cudaGetSymbolAddress((void**)&pss,    g_ss);

    cudaFuncSetAttribute(conv_mma_kernel, cudaFuncAttributeMaxDynamicSharedMemorySize, CONV_SMEM);

    wfrag_kernel<<<1728, 256>>>(conv_w, (uint4*)pwf, 4 * 110592);

    zero_kernel<<<1184, 256>>>(px, pcnt, M);
    encoder_kernel<<<1024, 256>>>(gp, w_enc, b_enc, ln_g, ln_b, inv_idx, px, pcnt, N);
    divide_pack_kernel<<<1184, 256>>>(px, pcnt, pp, M * C);

    const int convGrid = (M + 255) / 256;
    const uint4* wf = (const uint4*)pwf;
    // stage 0
    zero_stats_kernel<<<1, 256>>>(pstats);
    conv_mma_kernel<<<convGrid, 512, CONV_SMEM>>>(pp, py, wf + 0 * 110592, nbr_idx, nbr_mask, pstats, M);
    bnfinalize_kernel<<<1, 128>>>(pstats, bn_g + 0 * C, bn_b + 0 * C, pss, M);
    bnapply_kernel<<<1184, 256>>>(py, pss, nullptr, nullptr, pp, M * C);
    // stage 1 (+ residual x)
    zero_stats_kernel<<<1, 256>>>(pstats);
    conv_mma_kernel<<<convGrid, 512, CONV_SMEM>>>(pp, py, wf + 1 * 110592, nbr_idx, nbr_mask, pstats, M);
    bnfinalize_kernel<<<1, 128>>>(pstats, bn_g + 1 * C, bn_b + 1 * C, pss, M);
    bnapply_kernel<<<1184, 256>>>(py, pss, px, px, pp, M * C);
    // stage 2
    zero_stats_kernel<<<1, 256>>>(pstats);
    conv_mma_kernel<<<convGrid, 512, CONV_SMEM>>>(pp, py, wf + 2 * 110592, nbr_idx, nbr_mask, pstats, M);
    bnfinalize_kernel<<<1, 128>>>(pstats, bn_g + 2 * C, bn_b + 2 * C, pss, M);
    bnapply_kernel<<<1184, 256>>>(py, pss, nullptr, nullptr, pp, M * C);
    // stage 3 (+ residual x)
    zero_stats_kernel<<<1, 256>>>(pstats);
    conv_mma_kernel<<<convGrid, 512, CONV_SMEM>>>(pp, py, wf + 3 * 110592, nbr_idx, nbr_mask, pstats, M);
    bnfinalize_kernel<<<1, 128>>>(pstats, bn_g + 3 * C, bn_b + 3 * C, pss, M);
    bnapply_kernel<<<1184, 256>>>(py, pss, px, px, pp, M * C);

    head_kernel<<<1024, 256>>>(px, inv_idx, gp, w1, b1, w2, b2, out, N);
}